// round 12
// baseline (speedup 1.0000x reference)
#include <cuda_runtime.h>
#include <cuda_bf16.h>
#include <cstdint>

// ---------------------------------------------------------------------------
// Spiking Swin block:
//   q,k,v = lif(x @ W^T)  -> binary, bitpacked (literal reshape == flat bitpack)
//   attn  = SCALE*popc(q&k) + rpb          (written to d_out[8388608..])
//   out1  = attn @ v  (v binary; zero v-tile -> flag, no traffic)
//   out   = lif(out1 @ Wproj^T + bproj)    (written to d_out[0..8388608))
//
// Spike words use a fixed intra-byte bit permutation (shared by q/k/v):
//   word bit p  <->  channel (p & ~7) | ((p&3)<<1) | ((p>>2)&1)
// popc(q&k) is invariant; fallback paths decode explicitly.
// ---------------------------------------------------------------------------

#define TOK_TOTAL 16384          // B_*H*W = 256*64
#define SCALE_F   0.17677669529663687f

__device__ unsigned g_qbits[262144];
__device__ unsigned g_kbits[262144];
__device__ unsigned g_vbits[262144];
__device__ int      g_vnz[1024];       // per (b',head): v tile has any spike
__device__ float    g_out1[8388608];   // proj input; only written where flag!=0

#define PA 136   // bf16 pitch (272B rows: ldmatrix conflict-free)

__device__ __forceinline__ void ldsm4(uint32_t addr, unsigned& r0, unsigned& r1,
                                      unsigned& r2, unsigned& r3) {
    asm volatile("ldmatrix.sync.aligned.m8n8.x4.shared.b16 {%0,%1,%2,%3}, [%4];"
                 : "=r"(r0), "=r"(r1), "=r"(r2), "=r"(r3) : "r"(addr));
}

__device__ __forceinline__ void mma16816(float* c, unsigned a0, unsigned a1,
                                         unsigned a2, unsigned a3,
                                         unsigned b0, unsigned b1) {
    asm volatile(
        "mma.sync.aligned.m16n8k16.row.col.f32.bf16.bf16.f32 "
        "{%0,%1,%2,%3}, {%4,%5,%6,%7}, {%8,%9}, {%0,%1,%2,%3};"
        : "+f"(c[0]), "+f"(c[1]), "+f"(c[2]), "+f"(c[3])
        : "r"(a0), "r"(a1), "r"(a2), "r"(a3), "r"(b0), "r"(b1));
}

// ------------------------------- Stage A -----------------------------------
// C(128x128) = X_tile @ W^T in bf16 (spike bits exact: LIF margin >> bf16 err).
// A rows token-interleaved (row m <-> token m>>2, t=m&3) so each warp's tile
// holds all 4 timesteps of its tokens -> LIF in registers via shfl transpose,
// spike words via ballot. No epilogue smem, one __syncthreads total.
__global__ void __launch_bounds__(512, 2) gemm_qkv_lif_kernel(
    const float* __restrict__ x,
    const float* __restrict__ Wq,
    const float* __restrict__ Wk,
    const float* __restrict__ Wv)
{
    extern __shared__ char smem_raw[];
    __nv_bfloat16* Ah = (__nv_bfloat16*)smem_raw;      // 34816 B
    __nv_bfloat16* Bh = Ah + 128 * PA;                 // 34816 B

    const int tid = threadIdx.x;
    const int nb = blockIdx.y;                 // 0:q 1:k 2:v
    const int tokbase = blockIdx.x * 32;
    const float* W = (nb == 0) ? Wq : ((nb == 1) ? Wk : Wv);

    // ---- load. A row m <- x[t = m&3][token tokbase + (m>>2)]; B row m <- W[m]
#pragma unroll
    for (int it = 0; it < 8; ++it) {
        int idx = it * 512 + tid;              // float4 id, 4096 total
        int m = idx >> 5, c4 = idx & 31;
        int i = m >> 2, t = m & 3;
        float4 v4 = *(const float4*)(x + (size_t)(t * TOK_TOTAL + tokbase + i) * 128 + c4 * 4);
        __nv_bfloat162* d = (__nv_bfloat162*)(Ah + m * PA + c4 * 4);
        d[0] = __floats2bfloat162_rn(v4.x, v4.y);
        d[1] = __floats2bfloat162_rn(v4.z, v4.w);
        float4 w4 = *(const float4*)(W + (size_t)m * 128 + c4 * 4);
        __nv_bfloat162* dw = (__nv_bfloat162*)(Bh + m * PA + c4 * 4);
        dw[0] = __floats2bfloat162_rn(w4.x, w4.y);
        dw[1] = __floats2bfloat162_rn(w4.z, w4.w);
    }
    __syncthreads();

    const int w = tid >> 5, lane = tid & 31;
    const int wm = w & 3, wn = w >> 2;         // warp tile: 32 rows x 32 cols
    const int r8 = lane & 7;
    const int lb3 = (lane >> 3) & 1, lb4 = (lane >> 4) & 1;

    // ldmatrix x4 lane addresses (bytes, shared space)
    const uint32_t Abase = (uint32_t)__cvta_generic_to_shared(Ah);
    const uint32_t Bbase = (uint32_t)__cvta_generic_to_shared(Bh);
    // A: matrix m: row-half = m&1 (lb3), k-half = m>>1 (lb4)
    const uint32_t aaddr0 = Abase + (uint32_t)(((wm * 32 + lb3 * 8 + r8) * PA + lb4 * 8) * 2);
    const uint32_t aaddr1 = aaddr0 + 16 * PA * 2;
    // B: matrix m: k-half = m&1 (lb3), n-half = m>>1 (lb4)
    const uint32_t baddr0 = Bbase + (uint32_t)(((wn * 32 + lb4 * 8 + r8) * PA + lb3 * 8) * 2);
    const uint32_t baddr1 = baddr0 + 16 * PA * 2;

    float c[2][4][4];
#pragma unroll
    for (int mt = 0; mt < 2; ++mt)
#pragma unroll
        for (int nt = 0; nt < 4; ++nt)
#pragma unroll
            for (int r = 0; r < 4; ++r) c[mt][nt][r] = 0.f;

#pragma unroll
    for (int kk = 0; kk < 8; ++kk) {
        unsigned b0, b1, b2, b3, b4, b5, b6, b7;
        ldsm4(baddr0 + kk * 32, b0, b1, b2, b3);   // nt 0,1
        ldsm4(baddr1 + kk * 32, b4, b5, b6, b7);   // nt 2,3
        unsigned a0, a1, a2, a3;
        ldsm4(aaddr0 + kk * 32, a0, a1, a2, a3);   // mt 0
        mma16816(c[0][0], a0, a1, a2, a3, b0, b1);
        mma16816(c[0][1], a0, a1, a2, a3, b2, b3);
        mma16816(c[0][2], a0, a1, a2, a3, b4, b5);
        mma16816(c[0][3], a0, a1, a2, a3, b6, b7);
        ldsm4(aaddr1 + kk * 32, a0, a1, a2, a3);   // mt 1
        mma16816(c[1][0], a0, a1, a2, a3, b0, b1);
        mma16816(c[1][1], a0, a1, a2, a3, b2, b3);
        mma16816(c[1][2], a0, a1, a2, a3, b4, b5);
        mma16816(c[1][3], a0, a1, a2, a3, b6, b7);
    }

    // ---- register epilogue. Per (mt,nt): thread holds V[j]=c[..][j] with
    // j = 2*delta + cbit: (token Tb+2delta, chan cc+cbit) at t = k = (lane>>2)&3.
    // 4x4 shfl-butterfly transpose over lanes {l^4, l^8} puts each lane's own
    // (token,chan) t-series into V[0..3]; LIF -> 4 spike bits.
    const bool k0 = (lane & 4) != 0;
    const bool k1 = (lane & 8) != 0;
    unsigned sbp = 0;
#pragma unroll
    for (int mt = 0; mt < 2; ++mt)
#pragma unroll
        for (int nt = 0; nt < 4; ++nt) {
            float V0 = c[mt][nt][0], V1 = c[mt][nt][1];
            float V2 = c[mt][nt][2], V3 = c[mt][nt][3];
            // step 1 (mask 4): swap slot-bit0 with lane k-bit0
            float e0 = k0 ? V0 : V1;
            float e1 = k0 ? V2 : V3;
            float r0 = __shfl_xor_sync(0xffffffffu, e0, 4);
            float r1 = __shfl_xor_sync(0xffffffffu, e1, 4);
            V0 = k0 ? r0 : V0;  V1 = k0 ? V1 : r0;
            V2 = k0 ? r1 : V2;  V3 = k0 ? V3 : r1;
            // step 2 (mask 8): swap slot-bit1 with lane k-bit1
            float f0 = k1 ? V0 : V2;
            float f1 = k1 ? V1 : V3;
            float s0 = __shfl_xor_sync(0xffffffffu, f0, 8);
            float s1 = __shfl_xor_sync(0xffffffffu, f1, 8);
            V0 = k1 ? s0 : V0;  V2 = k1 ? V2 : s0;
            V1 = k1 ? s1 : V1;  V3 = k1 ? V3 : s1;
            // V[t] = y at t=0..3 for this lane's (token, channel); LIF:
            unsigned sb = 0;
            float v = V0 * 0.5f;
            if (v >= 1.0f) { sb |= 1u; v = 0.f; }
            v += (V1 - v) * 0.5f;
            if (v >= 1.0f) { sb |= 2u; v = 0.f; }
            v += (V2 - v) * 0.5f;
            if (v >= 1.0f) { sb |= 4u; v = 0.f; }
            v += (V3 - v) * 0.5f;
            if (v >= 1.0f) { sb |= 8u; }
            sbp |= sb << ((mt * 4 + nt) * 4);
        }

    // ---- word assembly via ballot. Writer lane l -> (t=l&3, token tau=l>>2).
    const int t_w  = lane & 3;
    const int tau  = lane >> 2;                // 0..7 within wm's 8 tokens
    const int mt_w = (lane >> 4) & 1;
    const int rem  = (lane >> 2) & 3;
    const int byteidx = ((rem & 1) << 1) | (rem >> 1);
    unsigned word = 0;
#pragma unroll
    for (int nt = 0; nt < 4; ++nt) {
        unsigned q00 = __ballot_sync(0xffffffffu, (sbp >> ((0 * 4 + nt) * 4 + 0)) & 1u);
        unsigned q01 = __ballot_sync(0xffffffffu, (sbp >> ((0 * 4 + nt) * 4 + 1)) & 1u);
        unsigned q02 = __ballot_sync(0xffffffffu, (sbp >> ((0 * 4 + nt) * 4 + 2)) & 1u);
        unsigned q03 = __ballot_sync(0xffffffffu, (sbp >> ((0 * 4 + nt) * 4 + 3)) & 1u);
        unsigned q10 = __ballot_sync(0xffffffffu, (sbp >> ((1 * 4 + nt) * 4 + 0)) & 1u);
        unsigned q11 = __ballot_sync(0xffffffffu, (sbp >> ((1 * 4 + nt) * 4 + 1)) & 1u);
        unsigned q12 = __ballot_sync(0xffffffffu, (sbp >> ((1 * 4 + nt) * 4 + 2)) & 1u);
        unsigned q13 = __ballot_sync(0xffffffffu, (sbp >> ((1 * 4 + nt) * 4 + 3)) & 1u);
        unsigned bm0 = mt_w ? q10 : q00;
        unsigned bm1 = mt_w ? q11 : q01;
        unsigned bm2 = mt_w ? q12 : q02;
        unsigned bm3 = mt_w ? q13 : q03;
        unsigned s01 = (t_w & 1) ? bm1 : bm0;
        unsigned s23 = (t_w & 1) ? bm3 : bm2;
        unsigned sel = (t_w & 2) ? s23 : s01;
        word |= ((sel >> (byteidx * 8)) & 0xffu) << (nt * 8);
    }
    unsigned* dst = (nb == 0) ? g_qbits : ((nb == 1) ? g_kbits : g_vbits);
    dst[(t_w * TOK_TOTAL + tokbase + wm * 8 + tau) * 4 + wn] = word;
}

// ------------------------------- Stage B -----------------------------------
// One block per (b', head): attn = SCALE*popc(q&k)+rpb -> d_out (float4,
// streaming stores); out1 = attn@v only if v has spikes (flag otherwise).
__global__ void __launch_bounds__(256) attn_kernel(
    const float* __restrict__ rpb_table, float* __restrict__ out)
{
    __shared__ unsigned qw[256], kw[256], vw[256];
    __shared__ float rpb_sm[1575];             // per-head slice, stride-1

    const int tid = threadIdx.x;
    const int bh = blockIdx.x;                 // = b'*4 + head
    const int bq = bh >> 2, head = bh & 3;

    qw[tid] = g_qbits[bh * 256 + tid];
    kw[tid] = g_kbits[bh * 256 + tid];
    vw[tid] = g_vbits[bh * 256 + tid];
    for (int idx = tid; idx < 1575; idx += 256)
        rpb_sm[idx] = rpb_table[idx * 4 + head];
    __syncthreads();

    const int u = tid & 63;                    // m-quad
    const int grp = tid >> 6;                  // n offset within group of 4
    unsigned km[4];
    int zm[4], ym[4], xm[4];
#pragma unroll
    for (int j = 0; j < 4; ++j) {
        int m = u * 4 + j;
        km[j] = kw[m];
        zm[j] = m >> 6; ym[j] = (m >> 3) & 7; xm[j] = m & 7;
    }
    float4* aout = (float4*)(out + 8388608 + (size_t)bh * 65536);
#pragma unroll 2
    for (int nb = 0; nb < 256; nb += 4) {
        int n = nb + grp;
        int zn = n >> 6, yn = (n >> 3) & 7, xn = n & 7;
        unsigned qn = qw[n];
        float4 r;
        {
            int ridx = (zn - zm[0] + 3) * 225 + (yn - ym[0] + 7) * 15 + (xn - xm[0] + 7);
            r.x = SCALE_F * (float)__popc(qn & km[0]) + rpb_sm[ridx];
        }
        {
            int ridx = (zn - zm[1] + 3) * 225 + (yn - ym[1] + 7) * 15 + (xn - xm[1] + 7);
            r.y = SCALE_F * (float)__popc(qn & km[1]) + rpb_sm[ridx];
        }
        {
            int ridx = (zn - zm[2] + 3) * 225 + (yn - ym[2] + 7) * 15 + (xn - xm[2] + 7);
            r.z = SCALE_F * (float)__popc(qn & km[2]) + rpb_sm[ridx];
        }
        {
            int ridx = (zn - zm[3] + 3) * 225 + (yn - ym[3] + 7) * 15 + (xn - xm[3] + 7);
            r.w = SCALE_F * (float)__popc(qn & km[3]) + rpb_sm[ridx];
        }
        __stcs(&aout[(size_t)n * 64 + u], r);
    }

    // out1 = attn @ v. Zero v tile -> flag only, no memory traffic.
    int vnz = __syncthreads_or(vw[tid] != 0u);
    if (tid == 0) g_vnz[bh] = vnz;
    if (vnz) {
        __shared__ int mlist[256];
        __shared__ int mcount;
        if (tid == 0) mcount = 0;
        __syncthreads();
        if (vw[tid] != 0u) { int p = atomicAdd(&mcount, 1); mlist[p] = tid; }
        __syncthreads();
        int cnt = mcount;
        for (int p = tid; p < 8192; p += 256) {
            int n = p >> 5, hd = p & 31;       // hd = permuted bit position
            int zn = n >> 6, yn = (n >> 3) & 7, xn = n & 7;
            unsigned qn = qw[n];
            float acc = 0.f;
            for (int j = 0; j < cnt; ++j) {
                int m = mlist[j];
                if ((vw[m] >> hd) & 1u) {
                    int zk = m >> 6, yk = (m >> 3) & 7, xk = m & 7;
                    int ridx = (zn - zk + 3) * 225 + (yn - yk + 7) * 15 + (xn - xk + 7);
                    acc += SCALE_F * (float)__popc(qn & kw[m]) + rpb_sm[ridx];
                }
            }
            // decode permuted bit position -> real channel offset
            int co = (hd & ~7) | ((hd & 3) << 1) | ((hd >> 2) & 1);
            int row2 = (n >> 6) * TOK_TOTAL + bq * 64 + (n & 63);
            g_out1[(size_t)row2 * 128 + head * 32 + co] = acc;
        }
    }
}

// ------------------------------- Stage C -----------------------------------
// Merged projection. Fast path (all 4 head flags zero, the expected case):
// y == bproj exactly -> spikes depend only on (t, channel); coalesced float4
// streaming stores. Fallback (never observed): full dot products from global,
// reading g_out1 only for flagged heads (unwritten regions are exact zeros).
__global__ void __launch_bounds__(256) proj_kernel(
    const float* __restrict__ Wproj, const float* __restrict__ bproj,
    float* __restrict__ dout)
{
    const int tg = blockIdx.x * 256 + threadIdx.x;
    float4* o4 = (float4*)dout;
#pragma unroll
    for (int k = 0; k < 4; ++k) {
        int L = tg * 4 + k;                    // float4 id in out spike region
        int row = L >> 5, c4 = L & 31;         // row = t*16384 + token
        int t = row >> 14, token = row & 16383, bq = token >> 6;
        int f0 = g_vnz[bq * 4 + 0], f1 = g_vnz[bq * 4 + 1];
        int f2 = g_vnz[bq * 4 + 2], f3 = g_vnz[bq * 4 + 3];
        if (!(f0 | f1 | f2 | f3)) {
            float4 b4 = ((const float4*)bproj)[c4];
            float4 v = make_float4(0.f, 0.f, 0.f, 0.f);
            float4 s = make_float4(0.f, 0.f, 0.f, 0.f);
            for (int tt = 0; tt <= t; ++tt) {
                v.x += (b4.x - v.x) * 0.5f; v.y += (b4.y - v.y) * 0.5f;
                v.z += (b4.z - v.z) * 0.5f; v.w += (b4.w - v.w) * 0.5f;
                s.x = (v.x >= 1.f) ? 1.f : 0.f; if (v.x >= 1.f) v.x = 0.f;
                s.y = (v.y >= 1.f) ? 1.f : 0.f; if (v.y >= 1.f) v.y = 0.f;
                s.z = (v.z >= 1.f) ? 1.f : 0.f; if (v.z >= 1.f) v.z = 0.f;
                s.w = (v.w >= 1.f) ? 1.f : 0.f; if (v.w >= 1.f) v.w = 0.f;
            }
            __stcs(&o4[L], s);
        } else {
            int hf[4] = {f0, f1, f2, f3};
            float4 s;
            float* sp = (float*)&s;
#pragma unroll
            for (int dd = 0; dd < 4; ++dd) {
                int d = c4 * 4 + dd;
                float bj = bproj[d];
                float v = 0.f, sv = 0.f;
                for (int tt = 0; tt <= t; ++tt) {
                    float y = bj;
                    for (int h = 0; h < 4; ++h) {
                        if (!hf[h]) continue;
                        const float* o1 = g_out1 + (size_t)(tt * TOK_TOTAL + token) * 128 + h * 32;
                        const float* wp = Wproj + (size_t)d * 128 + h * 32;
                        for (int kk = 0; kk < 32; ++kk) y += o1[kk] * wp[kk];
                    }
                    v += (y - v) * 0.5f;
                    sv = (v >= 1.f) ? 1.f : 0.f;
                    if (v >= 1.f) v = 0.f;
                }
                sp[dd] = sv;
            }
            __stcs(&o4[L], s);
        }
    }
}

// ---------------------------------------------------------------------------
extern "C" void kernel_launch(void* const* d_in, const int* in_sizes, int n_in,
                              void* d_out, int out_size) {
    const float* x   = (const float*)d_in[0];
    const float* Wq  = (const float*)d_in[1];
    const float* Wk  = (const float*)d_in[2];
    const float* Wv  = (const float*)d_in[3];
    const float* rpb = (const float*)d_in[4];
    const float* Wp  = (const float*)d_in[5];
    const float* bp  = (const float*)d_in[6];
    float* out = (float*)d_out;

    const int gemm_smem = 2 * 128 * PA * 2;            // 69632 B -> 2 CTAs/SM
    cudaFuncSetAttribute(gemm_qkv_lif_kernel,
                         cudaFuncAttributeMaxDynamicSharedMemorySize, gemm_smem);

    gemm_qkv_lif_kernel<<<dim3(512, 3), 512, gemm_smem>>>(x, Wq, Wk, Wv);
    attn_kernel<<<1024, 256>>>(rpb, out);
    proj_kernel<<<2048, 256>>>(Wp, bp, out);
}

// round 15
// speedup vs baseline: 1.0124x; 1.0124x over previous
#include <cuda_runtime.h>
#include <cuda_bf16.h>
#include <cstdint>

// ---------------------------------------------------------------------------
// Spiking Swin block:
//   q,k,v = lif(x @ W^T)  -> binary, bitpacked (literal reshape == flat bitpack)
//   attn  = SCALE*popc(q&k) + rpb          (written to d_out[8388608..])
//   out1  = attn @ v  (v binary; zero v-tile -> flag, no traffic)
//   out   = lif(out1 @ Wproj^T + bproj)    (written to d_out[0..8388608))
//
// Spike words use a fixed intra-byte bit permutation (shared by q/k/v):
//   word bit p  <->  channel (p & ~7) | ((p&3)<<1) | ((p>>2)&1)
// popc(q&k) is invariant; fallback paths decode explicitly.
// ---------------------------------------------------------------------------

#define TOK_TOTAL 16384          // B_*H*W = 256*64
#define SCALE_F   0.17677669529663687f

__device__ unsigned g_qbits[262144];
__device__ unsigned g_kbits[262144];
__device__ unsigned g_vbits[262144];
__device__ int      g_vnz[1024];       // per (b',head): v tile has any spike
__device__ float    g_out1[8388608];   // proj input; only written where flag!=0

#define PA 136   // bf16 pitch (272B rows: ldmatrix conflict-free)

__device__ __forceinline__ void ldsm4(uint32_t addr, unsigned& r0, unsigned& r1,
                                      unsigned& r2, unsigned& r3) {
    asm volatile("ldmatrix.sync.aligned.m8n8.x4.shared.b16 {%0,%1,%2,%3}, [%4];"
                 : "=r"(r0), "=r"(r1), "=r"(r2), "=r"(r3) : "r"(addr));
}

__device__ __forceinline__ void mma16816(float* c, unsigned a0, unsigned a1,
                                         unsigned a2, unsigned a3,
                                         unsigned b0, unsigned b1) {
    asm volatile(
        "mma.sync.aligned.m16n8k16.row.col.f32.bf16.bf16.f32 "
        "{%0,%1,%2,%3}, {%4,%5,%6,%7}, {%8,%9}, {%0,%1,%2,%3};"
        : "+f"(c[0]), "+f"(c[1]), "+f"(c[2]), "+f"(c[3])
        : "r"(a0), "r"(a1), "r"(a2), "r"(a3), "r"(b0), "r"(b1));
}

// ------------------------------- Stage A -----------------------------------
// C(128x128) = X_tile @ W^T in bf16 (spike bits exact: LIF margin >> bf16 err).
// A rows token-interleaved (row m <-> token m>>2, t=m&3); LIF in registers via
// shfl transpose, spike words via ballot. One __syncthreads total.
__global__ void __launch_bounds__(512, 2) gemm_qkv_lif_kernel(
    const float* __restrict__ x,
    const float* __restrict__ Wq,
    const float* __restrict__ Wk,
    const float* __restrict__ Wv)
{
    extern __shared__ char smem_raw[];
    __nv_bfloat16* Ah = (__nv_bfloat16*)smem_raw;      // 34816 B
    __nv_bfloat16* Bh = Ah + 128 * PA;                 // 34816 B

    const int tid = threadIdx.x;
    const int nb = blockIdx.y;                 // 0:q 1:k 2:v
    const int tokbase = blockIdx.x * 32;
    const float* W = (nb == 0) ? Wq : ((nb == 1) ? Wk : Wv);

    // ---- load. A row m <- x[t = m&3][token tokbase + (m>>2)]; B row m <- W[m]
#pragma unroll
    for (int it = 0; it < 8; ++it) {
        int idx = it * 512 + tid;              // float4 id, 4096 total
        int m = idx >> 5, c4 = idx & 31;
        int i = m >> 2, t = m & 3;
        float4 v4 = *(const float4*)(x + (size_t)(t * TOK_TOTAL + tokbase + i) * 128 + c4 * 4);
        __nv_bfloat162* d = (__nv_bfloat162*)(Ah + m * PA + c4 * 4);
        d[0] = __floats2bfloat162_rn(v4.x, v4.y);
        d[1] = __floats2bfloat162_rn(v4.z, v4.w);
        float4 w4 = *(const float4*)(W + (size_t)m * 128 + c4 * 4);
        __nv_bfloat162* dw = (__nv_bfloat162*)(Bh + m * PA + c4 * 4);
        dw[0] = __floats2bfloat162_rn(w4.x, w4.y);
        dw[1] = __floats2bfloat162_rn(w4.z, w4.w);
    }
    __syncthreads();

    const int w = tid >> 5, lane = tid & 31;
    const int wm = w & 3, wn = w >> 2;         // warp tile: 32 rows x 32 cols
    const int r8 = lane & 7;
    const int lb3 = (lane >> 3) & 1, lb4 = (lane >> 4) & 1;

    const uint32_t Abase = (uint32_t)__cvta_generic_to_shared(Ah);
    const uint32_t Bbase = (uint32_t)__cvta_generic_to_shared(Bh);
    const uint32_t aaddr0 = Abase + (uint32_t)(((wm * 32 + lb3 * 8 + r8) * PA + lb4 * 8) * 2);
    const uint32_t aaddr1 = aaddr0 + 16 * PA * 2;
    const uint32_t baddr0 = Bbase + (uint32_t)(((wn * 32 + lb4 * 8 + r8) * PA + lb3 * 8) * 2);
    const uint32_t baddr1 = baddr0 + 16 * PA * 2;

    float c[2][4][4];
#pragma unroll
    for (int mt = 0; mt < 2; ++mt)
#pragma unroll
        for (int nt = 0; nt < 4; ++nt)
#pragma unroll
            for (int r = 0; r < 4; ++r) c[mt][nt][r] = 0.f;

#pragma unroll
    for (int kk = 0; kk < 8; ++kk) {
        unsigned b0, b1, b2, b3, b4, b5, b6, b7;
        ldsm4(baddr0 + kk * 32, b0, b1, b2, b3);   // nt 0,1
        ldsm4(baddr1 + kk * 32, b4, b5, b6, b7);   // nt 2,3
        unsigned a0, a1, a2, a3;
        ldsm4(aaddr0 + kk * 32, a0, a1, a2, a3);   // mt 0
        mma16816(c[0][0], a0, a1, a2, a3, b0, b1);
        mma16816(c[0][1], a0, a1, a2, a3, b2, b3);
        mma16816(c[0][2], a0, a1, a2, a3, b4, b5);
        mma16816(c[0][3], a0, a1, a2, a3, b6, b7);
        ldsm4(aaddr1 + kk * 32, a0, a1, a2, a3);   // mt 1
        mma16816(c[1][0], a0, a1, a2, a3, b0, b1);
        mma16816(c[1][1], a0, a1, a2, a3, b2, b3);
        mma16816(c[1][2], a0, a1, a2, a3, b4, b5);
        mma16816(c[1][3], a0, a1, a2, a3, b6, b7);
    }

    // ---- register epilogue: 4x4 shfl-butterfly transpose -> LIF -> bits.
    const bool k0 = (lane & 4) != 0;
    const bool k1 = (lane & 8) != 0;
    unsigned sbp = 0;
#pragma unroll
    for (int mt = 0; mt < 2; ++mt)
#pragma unroll
        for (int nt = 0; nt < 4; ++nt) {
            float V0 = c[mt][nt][0], V1 = c[mt][nt][1];
            float V2 = c[mt][nt][2], V3 = c[mt][nt][3];
            float e0 = k0 ? V0 : V1;
            float e1 = k0 ? V2 : V3;
            float r0 = __shfl_xor_sync(0xffffffffu, e0, 4);
            float r1 = __shfl_xor_sync(0xffffffffu, e1, 4);
            V0 = k0 ? r0 : V0;  V1 = k0 ? V1 : r0;
            V2 = k0 ? r1 : V2;  V3 = k0 ? V3 : r1;
            float f0 = k1 ? V0 : V2;
            float f1 = k1 ? V1 : V3;
            float s0 = __shfl_xor_sync(0xffffffffu, f0, 8);
            float s1 = __shfl_xor_sync(0xffffffffu, f1, 8);
            V0 = k1 ? s0 : V0;  V2 = k1 ? V2 : s0;
            V1 = k1 ? s1 : V1;  V3 = k1 ? V3 : s1;
            unsigned sb = 0;
            float v = V0 * 0.5f;
            if (v >= 1.0f) { sb |= 1u; v = 0.f; }
            v += (V1 - v) * 0.5f;
            if (v >= 1.0f) { sb |= 2u; v = 0.f; }
            v += (V2 - v) * 0.5f;
            if (v >= 1.0f) { sb |= 4u; v = 0.f; }
            v += (V3 - v) * 0.5f;
            if (v >= 1.0f) { sb |= 8u; }
            sbp |= sb << ((mt * 4 + nt) * 4);
        }

    // ---- word assembly via ballot. Writer lane l -> (t=l&3, token tau=l>>2).
    const int t_w  = lane & 3;
    const int tau  = lane >> 2;
    const int mt_w = (lane >> 4) & 1;
    const int rem  = (lane >> 2) & 3;
    const int byteidx = ((rem & 1) << 1) | (rem >> 1);
    unsigned word = 0;
#pragma unroll
    for (int nt = 0; nt < 4; ++nt) {
        unsigned q00 = __ballot_sync(0xffffffffu, (sbp >> ((0 * 4 + nt) * 4 + 0)) & 1u);
        unsigned q01 = __ballot_sync(0xffffffffu, (sbp >> ((0 * 4 + nt) * 4 + 1)) & 1u);
        unsigned q02 = __ballot_sync(0xffffffffu, (sbp >> ((0 * 4 + nt) * 4 + 2)) & 1u);
        unsigned q03 = __ballot_sync(0xffffffffu, (sbp >> ((0 * 4 + nt) * 4 + 3)) & 1u);
        unsigned q10 = __ballot_sync(0xffffffffu, (sbp >> ((1 * 4 + nt) * 4 + 0)) & 1u);
        unsigned q11 = __ballot_sync(0xffffffffu, (sbp >> ((1 * 4 + nt) * 4 + 1)) & 1u);
        unsigned q12 = __ballot_sync(0xffffffffu, (sbp >> ((1 * 4 + nt) * 4 + 2)) & 1u);
        unsigned q13 = __ballot_sync(0xffffffffu, (sbp >> ((1 * 4 + nt) * 4 + 3)) & 1u);
        unsigned bm0 = mt_w ? q10 : q00;
        unsigned bm1 = mt_w ? q11 : q01;
        unsigned bm2 = mt_w ? q12 : q02;
        unsigned bm3 = mt_w ? q13 : q03;
        unsigned s01 = (t_w & 1) ? bm1 : bm0;
        unsigned s23 = (t_w & 1) ? bm3 : bm2;
        unsigned sel = (t_w & 2) ? s23 : s01;
        word |= ((sel >> (byteidx * 8)) & 0xffu) << (nt * 8);
    }
    unsigned* dst = (nb == 0) ? g_qbits : ((nb == 1) ? g_kbits : g_vbits);
    dst[(t_w * TOK_TOTAL + tokbase + wm * 8 + tau) * 4 + wn] = word;
}

// ------------------------------- Stage B -----------------------------------
// One block per (b', head). Fast path: q has NO spikes (expected; 7.7-sigma
// event otherwise) -> popc(q&k)==0 exactly -> attn = rpb[head] broadcast;
// pure table-read + streaming stores, no popc/cvt/fma. Generic path kept for
// arbitrary inputs. out1 = attn@v only if v has spikes.
__global__ void __launch_bounds__(256) attn_kernel(
    const float* __restrict__ rpb_table, float* __restrict__ out)
{
    __shared__ unsigned qw[256], kw[256], vw[256];
    __shared__ float rpb_sm[1575];             // per-head slice, stride-1
    __shared__ short e_sm[256];                // e[n] = zn*225 + yn*15 + xn

    const int tid = threadIdx.x;
    const int bh = blockIdx.x;                 // = b'*4 + head
    const int bq = bh >> 2, head = bh & 3;

    qw[tid] = g_qbits[bh * 256 + tid];
    kw[tid] = g_kbits[bh * 256 + tid];
    vw[tid] = g_vbits[bh * 256 + tid];
    e_sm[tid] = (short)((tid >> 6) * 225 + ((tid >> 3) & 7) * 15 + (tid & 7));
    for (int idx = tid; idx < 1575; idx += 256)
        rpb_sm[idx] = rpb_table[idx * 4 + head];

    int qnz = __syncthreads_or(qw[tid] != 0u);
    int vnz = __syncthreads_or(vw[tid] != 0u);
    if (tid == 0) g_vnz[bh] = vnz;

    const int u = tid & 63;                    // m-quad (m = u*4+j)
    const int grp = tid >> 6;                  // n offset within group of 4
    float4* aout = (float4*)(out + 8388608 + (size_t)bh * 65536);

    if (!qnz) {
        // attn(n, u*4+j) = rpb_sm[e[n] + r0 - j]: the quad shares (zm,ym),
        // xm = xm0 + j, so indices are consecutive descending.
        const int m0 = u * 4;
        const int r0 = 787 - ((m0 >> 6) * 225 + ((m0 >> 3) & 7) * 15 + (m0 & 7));
#pragma unroll 4
        for (int nb = 0; nb < 256; nb += 4) {
            int n = nb + grp;
            int r = (int)e_sm[n] + r0;
            float4 o;
            o.x = rpb_sm[r];
            o.y = rpb_sm[r - 1];
            o.z = rpb_sm[r - 2];
            o.w = rpb_sm[r - 3];
            __stcs(&aout[(size_t)n * 64 + u], o);
        }
    } else {
        unsigned km[4];
        int base[4];
#pragma unroll
        for (int j = 0; j < 4; ++j) {
            int m = u * 4 + j;
            km[j] = kw[m];
            base[j] = 787 - ((m >> 6) * 225 + ((m >> 3) & 7) * 15 + (m & 7));
        }
#pragma unroll 2
        for (int nb = 0; nb < 256; nb += 4) {
            int n = nb + grp;
            int en = (int)e_sm[n];
            unsigned qn = qw[n];
            float4 r;
            r.x = SCALE_F * (float)__popc(qn & km[0]) + rpb_sm[en + base[0]];
            r.y = SCALE_F * (float)__popc(qn & km[1]) + rpb_sm[en + base[1]];
            r.z = SCALE_F * (float)__popc(qn & km[2]) + rpb_sm[en + base[2]];
            r.w = SCALE_F * (float)__popc(qn & km[3]) + rpb_sm[en + base[3]];
            __stcs(&aout[(size_t)n * 64 + u], r);
        }
    }

    // out1 = attn @ v. Zero v tile -> flag only, no memory traffic.
    if (vnz) {
        __shared__ int mlist[256];
        __shared__ int mcount;
        if (tid == 0) mcount = 0;
        __syncthreads();
        if (vw[tid] != 0u) { int p = atomicAdd(&mcount, 1); mlist[p] = tid; }
        __syncthreads();
        int cnt = mcount;
        for (int p = tid; p < 8192; p += 256) {
            int n = p >> 5, hd = p & 31;       // hd = permuted bit position
            int en = (int)e_sm[n];
            unsigned qn = qw[n];
            float acc = 0.f;
            for (int j = 0; j < cnt; ++j) {
                int m = mlist[j];
                if ((vw[m] >> hd) & 1u) {
                    int bm = 787 - ((m >> 6) * 225 + ((m >> 3) & 7) * 15 + (m & 7));
                    acc += SCALE_F * (float)__popc(qn & kw[m]) + rpb_sm[en + bm];
                }
            }
            // decode permuted bit position -> real channel offset
            int co = (hd & ~7) | ((hd & 3) << 1) | ((hd >> 2) & 1);
            int row2 = (n >> 6) * TOK_TOTAL + bq * 64 + (n & 63);
            g_out1[(size_t)row2 * 128 + head * 32 + co] = acc;
        }
    }
}

// ------------------------------- Stage C -----------------------------------
// Merged projection. Fast path (all 4 head flags zero, the expected case):
// y == bproj exactly -> spikes depend only on (t, channel); coalesced float4
// streaming stores. Fallback (never observed): full dot products from global,
// reading g_out1 only for flagged heads (unwritten regions are exact zeros).
__global__ void __launch_bounds__(256) proj_kernel(
    const float* __restrict__ Wproj, const float* __restrict__ bproj,
    float* __restrict__ dout)
{
    const int tg = blockIdx.x * 256 + threadIdx.x;
    float4* o4 = (float4*)dout;
#pragma unroll
    for (int k = 0; k < 4; ++k) {
        int L = tg * 4 + k;                    // float4 id in out spike region
        int row = L >> 5, c4 = L & 31;         // row = t*16384 + token
        int t = row >> 14, token = row & 16383, bq = token >> 6;
        int f0 = g_vnz[bq * 4 + 0], f1 = g_vnz[bq * 4 + 1];
        int f2 = g_vnz[bq * 4 + 2], f3 = g_vnz[bq * 4 + 3];
        if (!(f0 | f1 | f2 | f3)) {
            float4 b4 = ((const float4*)bproj)[c4];
            float4 v = make_float4(0.f, 0.f, 0.f, 0.f);
            float4 s = make_float4(0.f, 0.f, 0.f, 0.f);
            for (int tt = 0; tt <= t; ++tt) {
                v.x += (b4.x - v.x) * 0.5f; v.y += (b4.y - v.y) * 0.5f;
                v.z += (b4.z - v.z) * 0.5f; v.w += (b4.w - v.w) * 0.5f;
                s.x = (v.x >= 1.f) ? 1.f : 0.f; if (v.x >= 1.f) v.x = 0.f;
                s.y = (v.y >= 1.f) ? 1.f : 0.f; if (v.y >= 1.f) v.y = 0.f;
                s.z = (v.z >= 1.f) ? 1.f : 0.f; if (v.z >= 1.f) v.z = 0.f;
                s.w = (v.w >= 1.f) ? 1.f : 0.f; if (v.w >= 1.f) v.w = 0.f;
            }
            __stcs(&o4[L], s);
        } else {
            int hf[4] = {f0, f1, f2, f3};
            float4 s;
            float* sp = (float*)&s;
#pragma unroll
            for (int dd = 0; dd < 4; ++dd) {
                int d = c4 * 4 + dd;
                float bj = bproj[d];
                float v = 0.f, sv = 0.f;
                for (int tt = 0; tt <= t; ++tt) {
                    float y = bj;
                    for (int h = 0; h < 4; ++h) {
                        if (!hf[h]) continue;
                        const float* o1 = g_out1 + (size_t)(tt * TOK_TOTAL + token) * 128 + h * 32;
                        const float* wp = Wproj + (size_t)d * 128 + h * 32;
                        for (int kk = 0; kk < 32; ++kk) y += o1[kk] * wp[kk];
                    }
                    v += (y - v) * 0.5f;
                    sv = (v >= 1.f) ? 1.f : 0.f;
                    if (v >= 1.f) v = 0.f;
                }
                sp[dd] = sv;
            }
            __stcs(&o4[L], s);
        }
    }
}

// ---------------------------------------------------------------------------
extern "C" void kernel_launch(void* const* d_in, const int* in_sizes, int n_in,
                              void* d_out, int out_size) {
    const float* x   = (const float*)d_in[0];
    const float* Wq  = (const float*)d_in[1];
    const float* Wk  = (const float*)d_in[2];
    const float* Wv  = (const float*)d_in[3];
    const float* rpb = (const float*)d_in[4];
    const float* Wp  = (const float*)d_in[5];
    const float* bp  = (const float*)d_in[6];
    float* out = (float*)d_out;

    const int gemm_smem = 2 * 128 * PA * 2;            // 69632 B -> 2 CTAs/SM
    cudaFuncSetAttribute(gemm_qkv_lif_kernel,
                         cudaFuncAttributeMaxDynamicSharedMemorySize, gemm_smem);

    gemm_qkv_lif_kernel<<<dim3(512, 3), 512, gemm_smem>>>(x, Wq, Wk, Wv);
    attn_kernel<<<1024, 256>>>(rpb, out);
    proj_kernel<<<2048, 256>>>(Wp, bp, out);
}

// round 16
// speedup vs baseline: 1.1287x; 1.1148x over previous
#include <cuda_runtime.h>
#include <cuda_bf16.h>
#include <cstdint>

// ---------------------------------------------------------------------------
// Spiking Swin block:
//   q,k,v = lif(x @ W^T)  -> binary, bitpacked (literal reshape == flat bitpack)
//   attn  = SCALE*popc(q&k) + rpb          (written to d_out[8388608..])
//   out1  = attn @ v  (v binary; zero v-tile -> flag, no traffic)
//   out   = lif(out1 @ Wproj^T + bproj)    (written to d_out[0..8388608))
// Spike words are in NATURAL channel-bit order (A rows carry t in bits 3-4,
// so each thread's accum fragment holds all 4 timesteps of one token).
// ---------------------------------------------------------------------------

#define TOK_TOTAL 16384          // B_*H*W = 256*64
#define SCALE_F   0.17677669529663687f

__device__ unsigned g_qbits[262144];
__device__ unsigned g_kbits[262144];
__device__ unsigned g_vbits[262144];
__device__ int      g_vnz[1024];       // per (b',head): v tile has any spike
__device__ float    g_out1[8388608];   // proj input; only written where flag!=0

#define PA 136   // bf16 pitch (272B rows: ldmatrix conflict-free)

__device__ __forceinline__ void ldsm4(uint32_t addr, unsigned& r0, unsigned& r1,
                                      unsigned& r2, unsigned& r3) {
    asm volatile("ldmatrix.sync.aligned.m8n8.x4.shared.b16 {%0,%1,%2,%3}, [%4];"
                 : "=r"(r0), "=r"(r1), "=r"(r2), "=r"(r3) : "r"(addr));
}

__device__ __forceinline__ void mma16816(float* c, unsigned a0, unsigned a1,
                                         unsigned a2, unsigned a3,
                                         unsigned b0, unsigned b1) {
    asm volatile(
        "mma.sync.aligned.m16n8k16.row.col.f32.bf16.bf16.f32 "
        "{%0,%1,%2,%3}, {%4,%5,%6,%7}, {%8,%9}, {%0,%1,%2,%3};"
        : "+f"(c[0]), "+f"(c[1]), "+f"(c[2]), "+f"(c[3])
        : "r"(a0), "r"(a1), "r"(a2), "r"(a3), "r"(b0), "r"(b1));
}

// ------------------------------- Stage A -----------------------------------
// C(128x128) = X_tile @ W^T in bf16 (spike bits exact: LIF margin >> bf16 err).
// A row R = wm*32 + t*8 + (token&7): thread fragment rows {g,g+8,g+16,g+24}
// are t=0..3 of token wm*8+g -> LIF directly on accumulators, no transpose.
__global__ void __launch_bounds__(512, 2) gemm_qkv_lif_kernel(
    const float* __restrict__ x,
    const float* __restrict__ Wq,
    const float* __restrict__ Wk,
    const float* __restrict__ Wv)
{
    extern __shared__ char smem_raw[];
    __nv_bfloat16* Ah = (__nv_bfloat16*)smem_raw;      // 34816 B
    __nv_bfloat16* Bh = Ah + 128 * PA;                 // 34816 B

    const int tid = threadIdx.x;
    const int nb = blockIdx.y;                 // 0:q 1:k 2:v
    const int tokbase = blockIdx.x * 32;
    const float* W = (nb == 0) ? Wq : ((nb == 1) ? Wk : Wv);

    // ---- load. A row m: t = (m>>3)&3, token = (m>>5)*8 + (m&7); B row m <- W[m]
#pragma unroll
    for (int it = 0; it < 8; ++it) {
        int idx = it * 512 + tid;              // float4 id, 4096 total
        int m = idx >> 5, c4 = idx & 31;
        int i = (m >> 5) * 8 + (m & 7);
        int t = (m >> 3) & 3;
        float4 v4 = *(const float4*)(x + (size_t)(t * TOK_TOTAL + tokbase + i) * 128 + c4 * 4);
        __nv_bfloat162* d = (__nv_bfloat162*)(Ah + m * PA + c4 * 4);
        d[0] = __floats2bfloat162_rn(v4.x, v4.y);
        d[1] = __floats2bfloat162_rn(v4.z, v4.w);
        float4 w4 = *(const float4*)(W + (size_t)m * 128 + c4 * 4);
        __nv_bfloat162* dw = (__nv_bfloat162*)(Bh + m * PA + c4 * 4);
        dw[0] = __floats2bfloat162_rn(w4.x, w4.y);
        dw[1] = __floats2bfloat162_rn(w4.z, w4.w);
    }
    __syncthreads();

    const int w = tid >> 5, lane = tid & 31;
    const int wm = w & 3, wn = w >> 2;         // warp tile: 32 rows x 32 cols
    const int r8 = lane & 7;
    const int lb3 = (lane >> 3) & 1, lb4 = (lane >> 4) & 1;

    const uint32_t Abase = (uint32_t)__cvta_generic_to_shared(Ah);
    const uint32_t Bbase = (uint32_t)__cvta_generic_to_shared(Bh);
    const uint32_t aaddr0 = Abase + (uint32_t)(((wm * 32 + lb3 * 8 + r8) * PA + lb4 * 8) * 2);
    const uint32_t aaddr1 = aaddr0 + 16 * PA * 2;
    const uint32_t baddr0 = Bbase + (uint32_t)(((wn * 32 + lb4 * 8 + r8) * PA + lb3 * 8) * 2);
    const uint32_t baddr1 = baddr0 + 16 * PA * 2;

    float c[2][4][4];
#pragma unroll
    for (int mt = 0; mt < 2; ++mt)
#pragma unroll
        for (int nt = 0; nt < 4; ++nt)
#pragma unroll
            for (int r = 0; r < 4; ++r) c[mt][nt][r] = 0.f;

#pragma unroll
    for (int kk = 0; kk < 8; ++kk) {
        unsigned b0, b1, b2, b3, b4, b5, b6, b7;
        ldsm4(baddr0 + kk * 32, b0, b1, b2, b3);   // nt 0,1
        ldsm4(baddr1 + kk * 32, b4, b5, b6, b7);   // nt 2,3
        unsigned a0, a1, a2, a3;
        ldsm4(aaddr0 + kk * 32, a0, a1, a2, a3);   // mt 0 (t=0,1)
        mma16816(c[0][0], a0, a1, a2, a3, b0, b1);
        mma16816(c[0][1], a0, a1, a2, a3, b2, b3);
        mma16816(c[0][2], a0, a1, a2, a3, b4, b5);
        mma16816(c[0][3], a0, a1, a2, a3, b6, b7);
        ldsm4(aaddr1 + kk * 32, a0, a1, a2, a3);   // mt 1 (t=2,3)
        mma16816(c[1][0], a0, a1, a2, a3, b0, b1);
        mma16816(c[1][1], a0, a1, a2, a3, b2, b3);
        mma16816(c[1][2], a0, a1, a2, a3, b4, b5);
        mma16816(c[1][3], a0, a1, a2, a3, b6, b7);
    }

    // ---- epilogue: LIF directly on accumulators.
    // Thread (g=lane>>2, tq=lane&3) holds, for nt and cbit in {0,1}:
    //   y(t=0)=c[0][nt][cbit], y(t=1)=c[0][nt][2+cbit],
    //   y(t=2)=c[1][nt][cbit], y(t=3)=c[1][nt][2+cbit]
    // for (token = tokbase + wm*8 + g, channel = wn*32 + nt*8 + tq*2 + cbit).
    // local[t] packs the 8 spike bits at positions nt*8 + cbit.
    unsigned local[4] = {0u, 0u, 0u, 0u};
#pragma unroll
    for (int nt = 0; nt < 4; ++nt)
#pragma unroll
        for (int cbit = 0; cbit < 2; ++cbit) {
            const unsigned pos = 1u << (nt * 8 + cbit);
            float v = c[0][nt][cbit] * 0.5f;
            if (v >= 1.0f) { local[0] |= pos; v = 0.f; }
            v += (c[0][nt][2 + cbit] - v) * 0.5f;
            if (v >= 1.0f) { local[1] |= pos; v = 0.f; }
            v += (c[1][nt][cbit] - v) * 0.5f;
            if (v >= 1.0f) { local[2] |= pos; v = 0.f; }
            v += (c[1][nt][2 + cbit] - v) * 0.5f;
            if (v >= 1.0f) { local[3] |= pos; }
        }

    // ---- word gather: writer lane l -> (token g_w=l>>2, t_w=l&3).
    // word bit p = nt*8 + tq*2 + cbit comes from lane (g_w*4+tq)'s local[t_w]
    // bit (nt*8+cbit): word = OR_tq (local_t[srcbase+tq] << 2*tq). Natural order.
    const int t_w = lane & 3;
    const int srcbase = lane & ~3;
    unsigned word = 0;
#pragma unroll
    for (int t = 0; t < 4; ++t) {
        unsigned v0 = __shfl_sync(0xffffffffu, local[t], srcbase + 0);
        unsigned v1 = __shfl_sync(0xffffffffu, local[t], srcbase + 1);
        unsigned v2 = __shfl_sync(0xffffffffu, local[t], srcbase + 2);
        unsigned v3 = __shfl_sync(0xffffffffu, local[t], srcbase + 3);
        if (t_w == t) word = v0 | (v1 << 2) | (v2 << 4) | (v3 << 6);
    }
    unsigned* dst = (nb == 0) ? g_qbits : ((nb == 1) ? g_kbits : g_vbits);
    dst[(t_w * TOK_TOTAL + tokbase + wm * 8 + (lane >> 2)) * 4 + wn] = word;
}

// ------------------------------- Stage B -----------------------------------
// One block per (b', head). Fast path: q has NO spikes (expected; 7.7-sigma
// event otherwise) -> popc(q&k)==0 exactly -> attn = rpb[head] broadcast;
// pure table-read + streaming stores. Generic path kept for arbitrary inputs.
// out1 = attn@v only if v has spikes.
__global__ void __launch_bounds__(256) attn_kernel(
    const float* __restrict__ rpb_table, float* __restrict__ out)
{
    __shared__ unsigned qw[256], kw[256], vw[256];
    __shared__ float rpb_sm[1575];             // per-head slice, stride-1
    __shared__ short e_sm[256];                // e[n] = zn*225 + yn*15 + xn

    const int tid = threadIdx.x;
    const int bh = blockIdx.x;                 // = b'*4 + head
    const int bq = bh >> 2, head = bh & 3;

    qw[tid] = g_qbits[bh * 256 + tid];
    kw[tid] = g_kbits[bh * 256 + tid];
    vw[tid] = g_vbits[bh * 256 + tid];
    e_sm[tid] = (short)((tid >> 6) * 225 + ((tid >> 3) & 7) * 15 + (tid & 7));
    for (int idx = tid; idx < 1575; idx += 256)
        rpb_sm[idx] = rpb_table[idx * 4 + head];

    int qnz = __syncthreads_or(qw[tid] != 0u);
    int vnz = __syncthreads_or(vw[tid] != 0u);
    if (tid == 0) g_vnz[bh] = vnz;

    const int u = tid & 63;                    // m-quad (m = u*4+j)
    const int grp = tid >> 6;                  // n offset within group of 4
    float4* aout = (float4*)(out + 8388608 + (size_t)bh * 65536);

    if (!qnz) {
        // attn(n, u*4+j) = rpb_sm[e[n] + r0 - j]: the quad shares (zm,ym),
        // xm = xm0 + j, so indices are consecutive descending.
        const int m0 = u * 4;
        const int r0 = 787 - ((m0 >> 6) * 225 + ((m0 >> 3) & 7) * 15 + (m0 & 7));
#pragma unroll 4
        for (int nb = 0; nb < 256; nb += 4) {
            int n = nb + grp;
            int r = (int)e_sm[n] + r0;
            float4 o;
            o.x = rpb_sm[r];
            o.y = rpb_sm[r - 1];
            o.z = rpb_sm[r - 2];
            o.w = rpb_sm[r - 3];
            __stcs(&aout[(size_t)n * 64 + u], o);
        }
    } else {
        unsigned km[4];
        int base[4];
#pragma unroll
        for (int j = 0; j < 4; ++j) {
            int m = u * 4 + j;
            km[j] = kw[m];
            base[j] = 787 - ((m >> 6) * 225 + ((m >> 3) & 7) * 15 + (m & 7));
        }
#pragma unroll 2
        for (int nb = 0; nb < 256; nb += 4) {
            int n = nb + grp;
            int en = (int)e_sm[n];
            unsigned qn = qw[n];
            float4 r;
            r.x = SCALE_F * (float)__popc(qn & km[0]) + rpb_sm[en + base[0]];
            r.y = SCALE_F * (float)__popc(qn & km[1]) + rpb_sm[en + base[1]];
            r.z = SCALE_F * (float)__popc(qn & km[2]) + rpb_sm[en + base[2]];
            r.w = SCALE_F * (float)__popc(qn & km[3]) + rpb_sm[en + base[3]];
            __stcs(&aout[(size_t)n * 64 + u], r);
        }
    }

    // out1 = attn @ v. Zero v tile -> flag only, no memory traffic.
    if (vnz) {
        __shared__ int mlist[256];
        __shared__ int mcount;
        if (tid == 0) mcount = 0;
        __syncthreads();
        if (vw[tid] != 0u) { int p = atomicAdd(&mcount, 1); mlist[p] = tid; }
        __syncthreads();
        int cnt = mcount;
        for (int p = tid; p < 8192; p += 256) {
            int n = p >> 5, hd = p & 31;       // hd = channel offset (natural)
            int en = (int)e_sm[n];
            unsigned qn = qw[n];
            float acc = 0.f;
            for (int j = 0; j < cnt; ++j) {
                int m = mlist[j];
                if ((vw[m] >> hd) & 1u) {
                    int bm = 787 - ((m >> 6) * 225 + ((m >> 3) & 7) * 15 + (m & 7));
                    acc += SCALE_F * (float)__popc(qn & kw[m]) + rpb_sm[en + bm];
                }
            }
            int row2 = (n >> 6) * TOK_TOTAL + bq * 64 + (n & 63);
            g_out1[(size_t)row2 * 128 + head * 32 + hd] = acc;
        }
    }
}

// ------------------------------- Stage C -----------------------------------
// Merged projection. Fast path (all 4 head flags zero, the expected case):
// y == bproj exactly -> spikes depend only on (t, channel); coalesced float4
// streaming stores. Fallback (never observed): full dot products from global,
// reading g_out1 only for flagged heads (unwritten regions are exact zeros).
__global__ void __launch_bounds__(256) proj_kernel(
    const float* __restrict__ Wproj, const float* __restrict__ bproj,
    float* __restrict__ dout)
{
    const int tg = blockIdx.x * 256 + threadIdx.x;
    float4* o4 = (float4*)dout;
#pragma unroll
    for (int k = 0; k < 4; ++k) {
        int L = tg * 4 + k;                    // float4 id in out spike region
        int row = L >> 5, c4 = L & 31;         // row = t*16384 + token
        int t = row >> 14, token = row & 16383, bq = token >> 6;
        int f0 = g_vnz[bq * 4 + 0], f1 = g_vnz[bq * 4 + 1];
        int f2 = g_vnz[bq * 4 + 2], f3 = g_vnz[bq * 4 + 3];
        if (!(f0 | f1 | f2 | f3)) {
            float4 b4 = ((const float4*)bproj)[c4];
            float4 v = make_float4(0.f, 0.f, 0.f, 0.f);
            float4 s = make_float4(0.f, 0.f, 0.f, 0.f);
            for (int tt = 0; tt <= t; ++tt) {
                v.x += (b4.x - v.x) * 0.5f; v.y += (b4.y - v.y) * 0.5f;
                v.z += (b4.z - v.z) * 0.5f; v.w += (b4.w - v.w) * 0.5f;
                s.x = (v.x >= 1.f) ? 1.f : 0.f; if (v.x >= 1.f) v.x = 0.f;
                s.y = (v.y >= 1.f) ? 1.f : 0.f; if (v.y >= 1.f) v.y = 0.f;
                s.z = (v.z >= 1.f) ? 1.f : 0.f; if (v.z >= 1.f) v.z = 0.f;
                s.w = (v.w >= 1.f) ? 1.f : 0.f; if (v.w >= 1.f) v.w = 0.f;
            }
            __stcs(&o4[L], s);
        } else {
            int hf[4] = {f0, f1, f2, f3};
            float4 s;
            float* sp = (float*)&s;
#pragma unroll
            for (int dd = 0; dd < 4; ++dd) {
                int d = c4 * 4 + dd;
                float bj = bproj[d];
                float v = 0.f, sv = 0.f;
                for (int tt = 0; tt <= t; ++tt) {
                    float y = bj;
                    for (int h = 0; h < 4; ++h) {
                        if (!hf[h]) continue;
                        const float* o1 = g_out1 + (size_t)(tt * TOK_TOTAL + token) * 128 + h * 32;
                        const float* wp = Wproj + (size_t)d * 128 + h * 32;
                        for (int kk = 0; kk < 32; ++kk) y += o1[kk] * wp[kk];
                    }
                    v += (y - v) * 0.5f;
                    sv = (v >= 1.f) ? 1.f : 0.f;
                    if (v >= 1.f) v = 0.f;
                }
                sp[dd] = sv;
            }
            __stcs(&o4[L], s);
        }
    }
}

// ---------------------------------------------------------------------------
extern "C" void kernel_launch(void* const* d_in, const int* in_sizes, int n_in,
                              void* d_out, int out_size) {
    const float* x   = (const float*)d_in[0];
    const float* Wq  = (const float*)d_in[1];
    const float* Wk  = (const float*)d_in[2];
    const float* Wv  = (const float*)d_in[3];
    const float* rpb = (const float*)d_in[4];
    const float* Wp  = (const float*)d_in[5];
    const float* bp  = (const float*)d_in[6];
    float* out = (float*)d_out;

    const int gemm_smem = 2 * 128 * PA * 2;            // 69632 B -> 2 CTAs/SM
    cudaFuncSetAttribute(gemm_qkv_lif_kernel,
                         cudaFuncAttributeMaxDynamicSharedMemorySize, gemm_smem);

    gemm_qkv_lif_kernel<<<dim3(512, 3), 512, gemm_smem>>>(x, Wq, Wk, Wv);
    attn_kernel<<<1024, 256>>>(rpb, out);
    proj_kernel<<<2048, 256>>>(Wp, bp, out);
}